// round 2
// baseline (speedup 1.0000x reference)
#include <cuda_runtime.h>
#include <cuda_bf16.h>
#include <cstddef>

constexpr int Bn = 8;
constexpr int Tn = 2304;
constexpr int NROW = Bn * Tn;
constexpr float LAMBDA_INIT_F = 0.6192834728526787f;
constexpr float QSCALE = 0.18033688011112042f;   // (1/8) * log2(e)

__device__ float g_stats[NROW * 2];
__device__ float g_q[NROW * 128];
__device__ float g_k[NROW * 128];
__device__ float g_v[NROW * 128];
__device__ float g_lam;

__device__ __forceinline__ float fast_exp2(float x) {
  x = fmaxf(x, -125.0f);
  float t = x + 12582912.0f;
  int e = __float_as_int(t) - 0x4B400000;
  float f = x - (t - 12582912.0f);
  float p =        1.3333558e-3f;
  p = fmaf(p, f,   9.6181291e-3f);
  p = fmaf(p, f,   5.5504109e-2f);
  p = fmaf(p, f,   2.4022651e-1f);
  p = fmaf(p, f,   6.9314718e-1f);
  p = fmaf(p, f,   1.0f);
  return __int_as_float(__float_as_int(p) + (e << 23));
}

__device__ __forceinline__ float redsum16(float v) {
  v += __shfl_xor_sync(0xffffffffu, v, 8);
  v += __shfl_xor_sync(0xffffffffu, v, 4);
  v += __shfl_xor_sync(0xffffffffu, v, 2);
  v += __shfl_xor_sync(0xffffffffu, v, 1);
  return v;
}
__device__ __forceinline__ float redmax16(float v) {
  v = fmaxf(v, __shfl_xor_sync(0xffffffffu, v, 8));
  v = fmaxf(v, __shfl_xor_sync(0xffffffffu, v, 4));
  v = fmaxf(v, __shfl_xor_sync(0xffffffffu, v, 2));
  v = fmaxf(v, __shfl_xor_sync(0xffffffffu, v, 1));
  return v;
}

// ---------------- lambda ----------------
__global__ void lambda_kernel(const float* __restrict__ lq1,
                              const float* __restrict__ lq2,
                              const float* __restrict__ lk1,
                              const float* __restrict__ lk2) {
  __shared__ float sh1[64], sh2[64];
  int t = threadIdx.x;
  sh1[t] = lq1[t] * lk1[t];
  sh2[t] = lq2[t] * lk2[t];
  __syncthreads();
  if (t == 0) {
    float a = 0.f, c = 0.f;
    for (int i = 0; i < 64; i++) { a += sh1[i]; c += sh2[i]; }
    g_lam = expf(a) - expf(c) + LAMBDA_INIT_F;
  }
}

// ---------------- LN stats ----------------
__global__ void stats_kernel(const float* __restrict__ x) {
  int row = blockIdx.x * 8 + threadIdx.y;
  const float4* xr = (const float4*)(x + (size_t)row * 1024);
  float s = 0.f, ss = 0.f;
  for (int i = threadIdx.x; i < 256; i += 32) {
    float4 v = xr[i];
    s += v.x + v.y + v.z + v.w;
    ss += v.x * v.x + v.y * v.y + v.z * v.z + v.w * v.w;
  }
#pragma unroll
  for (int o = 16; o > 0; o >>= 1) {
    s += __shfl_xor_sync(0xffffffffu, s, o);
    ss += __shfl_xor_sync(0xffffffffu, ss, o);
  }
  if (threadIdx.x == 0) {
    float mean = s * (1.0f / 1024.0f);
    float var = fmaf(-mean, mean, ss * (1.0f / 1024.0f));
    g_stats[row * 2 + 0] = mean;
    g_stats[row * 2 + 1] = rsqrtf(var + 1e-5f);
  }
}

// ---------------- LN-fused projection GEMM ----------------
struct ProjParams {
  const float* x;
  const float* W[3][3];
  const float* g[3];
  const float* bta[3];
};

__global__ __launch_bounds__(256) void proj_kernel(ProjParams p) {
  __shared__ float As[16][68];
  __shared__ float Bs[16][132];
  __shared__ float mean_s[64], rstd_s[64];

  const int tile = blockIdx.x, bb = blockIdx.y, mat = blockIdx.z;
  const int seg = tile < 2 ? 0 : (tile < 34 ? 1 : 2);
  const float* __restrict__ W = p.W[mat][seg];
  const float* __restrict__ gg = p.g[seg];
  const float* __restrict__ bz = p.bta[seg];
  const int row0 = bb * Tn + tile * 64;
  const int tid = threadIdx.x;

  if (tid < 64) {
    mean_s[tid] = g_stats[(row0 + tid) * 2 + 0];
    rstd_s[tid] = g_stats[(row0 + tid) * 2 + 1];
  }

  const int rg = tid >> 4, ct = tid & 15;
  const int r0 = rg * 4, cc0 = ct * 8;
  const int ar = tid >> 2, ak = (tid & 3) * 4;

  float acc[4][8];
#pragma unroll
  for (int i = 0; i < 4; i++)
#pragma unroll
    for (int j = 0; j < 8; j++) acc[i][j] = 0.f;

  for (int k0 = 0; k0 < 1024; k0 += 16) {
    __syncthreads();
    {
      float4 v = *(const float4*)&p.x[(size_t)(row0 + ar) * 1024 + k0 + ak];
      float mn = mean_s[ar], rs = rstd_s[ar];
      As[ak + 0][ar] = (v.x - mn) * rs * gg[k0 + ak + 0] + bz[k0 + ak + 0];
      As[ak + 1][ar] = (v.y - mn) * rs * gg[k0 + ak + 1] + bz[k0 + ak + 1];
      As[ak + 2][ar] = (v.z - mn) * rs * gg[k0 + ak + 2] + bz[k0 + ak + 2];
      As[ak + 3][ar] = (v.w - mn) * rs * gg[k0 + ak + 3] + bz[k0 + ak + 3];
      float4 w0 = *(const float4*)&W[(size_t)(k0 + rg) * 128 + cc0];
      float4 w1 = *(const float4*)&W[(size_t)(k0 + rg) * 128 + cc0 + 4];
      *(float4*)&Bs[rg][cc0] = w0;
      *(float4*)&Bs[rg][cc0 + 4] = w1;
    }
    __syncthreads();
#pragma unroll
    for (int kk = 0; kk < 16; kk++) {
      float4 a4 = *(const float4*)&As[kk][r0];
      float4 b0 = *(const float4*)&Bs[kk][cc0];
      float4 b1 = *(const float4*)&Bs[kk][cc0 + 4];
      float av[4] = {a4.x, a4.y, a4.z, a4.w};
      float bv[8] = {b0.x, b0.y, b0.z, b0.w, b1.x, b1.y, b1.z, b1.w};
#pragma unroll
      for (int i = 0; i < 4; i++)
#pragma unroll
        for (int j = 0; j < 8; j++) acc[i][j] = fmaf(av[i], bv[j], acc[i][j]);
    }
  }

  float* __restrict__ outp = (mat == 0) ? g_q : (mat == 1) ? g_k : g_v;
#pragma unroll
  for (int i = 0; i < 4; i++) {
    size_t off = (size_t)(row0 + r0 + i) * 128 + cc0;
    *(float4*)&outp[off]     = make_float4(acc[i][0], acc[i][1], acc[i][2], acc[i][3]);
    *(float4*)&outp[off + 4] = make_float4(acc[i][4], acc[i][5], acc[i][6], acc[i][7]);
  }
}

// ---------------- dual flash attention + combine + out-LN ----------------
constexpr int ATTN_SMEM_FLOATS = 6 * 4352 + 64 * 132;
constexpr int ATTN_SMEM_BYTES = ATTN_SMEM_FLOATS * 4;   // 138240

__global__ __launch_bounds__(256, 1) void attn_kernel(
    const float* __restrict__ gam, const float* __restrict__ bet,
    float* __restrict__ out) {
  extern __shared__ float sm[];
  float* Qs1 = sm;
  float* Qs2 = sm + 4352;
  float* Ks1 = sm + 2 * 4352;
  float* Ks2 = sm + 3 * 4352;
  float* Ps1 = sm + 4 * 4352;
  float* Ps2 = sm + 5 * 4352;
  float* Vs  = sm + 6 * 4352;

  const int tid = threadIdx.x;
  const int rg = tid >> 4, ct = tid & 15;
  const int r0 = rg * 4, c0 = ct * 4, cv0 = ct * 8;
  const size_t base = (size_t)blockIdx.y * Tn;
  const float lam = g_lam;
  const float4 gv0 = *(const float4*)&gam[cv0];
  const float4 gv1 = *(const float4*)&gam[cv0 + 4];
  const float4 bv0 = *(const float4*)&bet[cv0];
  const float4 bv1 = *(const float4*)&bet[cv0 + 4];

  for (int half = 0; half < 2; half++) {
    const int qt = half ? (35 - (int)blockIdx.x) : (int)blockIdx.x;
    const int q0 = qt * 64;

    __syncthreads();
    for (int i = tid; i < 2048; i += 256) {
      int r = i >> 5, quad = i & 31;
      float4 v = *(const float4*)&g_q[(base + q0 + r) * 128 + quad * 4];
      float* dst = (quad < 16) ? Qs1 : Qs2;
      int dd = (quad * 4) & 63;
      dst[(dd + 0) * 68 + r] = v.x;
      dst[(dd + 1) * 68 + r] = v.y;
      dst[(dd + 2) * 68 + r] = v.z;
      dst[(dd + 3) * 68 + r] = v.w;
    }

    float O1[4][8], O2[4][8], m1[4], m2[4], l1[4], l2[4];
#pragma unroll
    for (int i = 0; i < 4; i++) {
      m1[i] = m2[i] = -3.0e38f;
      l1[i] = l2[i] = 0.f;
#pragma unroll
      for (int j = 0; j < 8; j++) { O1[i][j] = 0.f; O2[i][j] = 0.f; }
    }

    for (int kt = 0; kt <= qt; kt++) {
      const int k0 = kt * 64;
      __syncthreads();
      for (int i = tid; i < 2048; i += 256) {
        int c = i >> 5, quad = i & 31;
        float4 kv = *(const float4*)&g_k[(base + k0 + c) * 128 + quad * 4];
        float* dst = (quad < 16) ? Ks1 : Ks2;
        int dd = (quad * 4) & 63;
        dst[(dd + 0) * 68 + c] = kv.x;
        dst[(dd + 1) * 68 + c] = kv.y;
        dst[(dd + 2) * 68 + c] = kv.z;
        dst[(dd + 3) * 68 + c] = kv.w;
        float4 vv = *(const float4*)&g_v[(base + k0 + c) * 128 + quad * 4];
        *(float4*)&Vs[c * 132 + quad * 4] = vv;
      }
      __syncthreads();

      float s1[4][4], s2[4][4];
#pragma unroll
      for (int i = 0; i < 4; i++)
#pragma unroll
        for (int j = 0; j < 4; j++) { s1[i][j] = 0.f; s2[i][j] = 0.f; }

      for (int d = 0; d < 64; d++) {
        float4 qa = *(const float4*)&Qs1[d * 68 + r0];
        float4 ka = *(const float4*)&Ks1[d * 68 + c0];
        float4 qb = *(const float4*)&Qs2[d * 68 + r0];
        float4 kb = *(const float4*)&Ks2[d * 68 + c0];
        float q1v[4] = {qa.x, qa.y, qa.z, qa.w};
        float k1v[4] = {ka.x, ka.y, ka.z, ka.w};
        float q2v[4] = {qb.x, qb.y, qb.z, qb.w};
        float k2v[4] = {kb.x, kb.y, kb.z, kb.w};
#pragma unroll
        for (int i = 0; i < 4; i++)
#pragma unroll
          for (int j = 0; j < 4; j++) {
            s1[i][j] = fmaf(q1v[i], k1v[j], s1[i][j]);
            s2[i][j] = fmaf(q2v[i], k2v[j], s2[i][j]);
          }
      }

      const bool diag = (kt == qt);
      float p1[4][4], p2[4][4];
#pragma unroll
      for (int i = 0; i < 4; i++) {
        float mx1 = -3.0e38f, mx2 = -3.0e38f;
#pragma unroll
        for (int j = 0; j < 4; j++) {
          float a = s1[i][j] * QSCALE;
          float b = s2[i][j] * QSCALE;
          if (diag && (c0 + j) > (r0 + i)) { a = -3.0e38f; b = -3.0e38f; }
          s1[i][j] = a; s2[i][j] = b;
          mx1 = fmaxf(mx1, a); mx2 = fmaxf(mx2, b);
        }
        mx1 = redmax16(mx1);
        mx2 = redmax16(mx2);
        float mn1 = fmaxf(m1[i], mx1), mn2 = fmaxf(m2[i], mx2);
        float al1 = fast_exp2(m1[i] - mn1), al2 = fast_exp2(m2[i] - mn2);
        m1[i] = mn1; m2[i] = mn2;
        float su1 = 0.f, su2 = 0.f;
#pragma unroll
        for (int j = 0; j < 4; j++) {
          float e1 = fast_exp2(s1[i][j] - mn1);
          float e2 = fast_exp2(s2[i][j] - mn2);
          p1[i][j] = e1; p2[i][j] = e2;
          su1 += e1; su2 += e2;
        }
        su1 = redsum16(su1);
        su2 = redsum16(su2);
        l1[i] = l1[i] * al1 + su1;
        l2[i] = l2[i] * al2 + su2;
#pragma unroll
        for (int j = 0; j < 8; j++) { O1[i][j] *= al1; O2[i][j] *= al2; }
      }
#pragma unroll
      for (int j = 0; j < 4; j++) {
        *(float4*)&Ps1[(c0 + j) * 68 + r0] =
            make_float4(p1[0][j], p1[1][j], p1[2][j], p1[3][j]);
        *(float4*)&Ps2[(c0 + j) * 68 + r0] =
            make_float4(p2[0][j], p2[1][j], p2[2][j], p2[3][j]);
      }
      __syncthreads();

      for (int c = 0; c < 64; c++) {
        float4 pa = *(const float4*)&Ps1[c * 68 + r0];
        float4 pb = *(const float4*)&Ps2[c * 68 + r0];
        float4 va = *(const float4*)&Vs[c * 132 + cv0];
        float4 vb = *(const float4*)&Vs[c * 132 + cv0 + 4];
        float pav[4] = {pa.x, pa.y, pa.z, pa.w};
        float pbv[4] = {pb.x, pb.y, pb.z, pb.w};
        float vv[8] = {va.x, va.y, va.z, va.w, vb.x, vb.y, vb.z, vb.w};
#pragma unroll
        for (int i = 0; i < 4; i++)
#pragma unroll
          for (int j = 0; j < 8; j++) {
            O1[i][j] = fmaf(pav[i], vv[j], O1[i][j]);
            O2[i][j] = fmaf(pbv[i], vv[j], O2[i][j]);
          }
      }
    }

    // epilogue: combine + output LN
#pragma unroll
    for (int i = 0; i < 4; i++) {
      float inv1 = 1.0f / l1[i], inv2 = lam / l2[i];
      float att[8];
      float s = 0.f;
#pragma unroll
      for (int j = 0; j < 8; j++) {
        att[j] = O1[i][j] * inv1 - O2[i][j] * inv2;
        s += att[j];
      }
      float mean = redsum16(s) * (1.0f / 128.0f);
      float vs = 0.f;
#pragma unroll
      for (int j = 0; j < 8; j++) {
        float d = att[j] - mean;
        vs += d * d;
      }
      float var = redsum16(vs) * (1.0f / 128.0f);
      float rstd = rsqrtf(var + 1e-5f);
      float g8[8] = {gv0.x, gv0.y, gv0.z, gv0.w, gv1.x, gv1.y, gv1.z, gv1.w};
      float b8[8] = {bv0.x, bv0.y, bv0.z, bv0.w, bv1.x, bv1.y, bv1.z, bv1.w};
      float o[8];
#pragma unroll
      for (int j = 0; j < 8; j++)
        o[j] = (att[j] - mean) * rstd * g8[j] + b8[j];
      size_t off = (base + q0 + r0 + i) * 128 + cv0;
      *(float4*)&out[off]     = make_float4(o[0], o[1], o[2], o[3]);
      *(float4*)&out[off + 4] = make_float4(o[4], o[5], o[6], o[7]);
    }
  }
}

// ---------------- launch ----------------
extern "C" void kernel_launch(void* const* d_in, const int* in_sizes, int n_in,
                              void* d_out, int out_size) {
  const float* x     = (const float*)d_in[0];
  const float* Wq    = (const float*)d_in[1];
  const float* Wk    = (const float*)d_in[2];
  const float* Wv    = (const float*)d_in[3];
  const float* Wq_ss = (const float*)d_in[4];
  const float* Wk_ss = (const float*)d_in[5];
  const float* Wv_ss = (const float*)d_in[6];
  const float* Wq_se = (const float*)d_in[7];
  const float* Wk_se = (const float*)d_in[8];
  const float* Wv_se = (const float*)d_in[9];
  const float* g_in  = (const float*)d_in[10];
  const float* b_in  = (const float*)d_in[11];
  const float* g_ss  = (const float*)d_in[12];
  const float* b_ss  = (const float*)d_in[13];
  const float* g_se  = (const float*)d_in[14];
  const float* b_se  = (const float*)d_in[15];
  const float* g_out = (const float*)d_in[16];
  const float* b_out = (const float*)d_in[17];
  const float* lq1   = (const float*)d_in[18];
  const float* lq2   = (const float*)d_in[19];
  const float* lk1   = (const float*)d_in[20];
  const float* lk2   = (const float*)d_in[21];

  static bool attr_set = false;
  if (!attr_set) {
    cudaFuncSetAttribute(attn_kernel, cudaFuncAttributeMaxDynamicSharedMemorySize,
                         ATTN_SMEM_BYTES);
    attr_set = true;
  }

  lambda_kernel<<<1, 64>>>(lq1, lq2, lk1, lk2);
  stats_kernel<<<NROW / 8, dim3(32, 8)>>>(x);

  ProjParams p;
  p.x = x;
  p.W[0][0] = Wq_ss; p.W[0][1] = Wq; p.W[0][2] = Wq_se;
  p.W[1][0] = Wk_ss; p.W[1][1] = Wk; p.W[1][2] = Wk_se;
  p.W[2][0] = Wv_ss; p.W[2][1] = Wv; p.W[2][2] = Wv_se;
  p.g[0] = g_ss; p.g[1] = g_in; p.g[2] = g_se;
  p.bta[0] = b_ss; p.bta[1] = b_in; p.bta[2] = b_se;
  proj_kernel<<<dim3(36, 8, 3), 256>>>(p);

  attn_kernel<<<dim3(18, 8), 256, ATTN_SMEM_BYTES>>>(g_out, b_out, (float*)d_out);
}